// round 1
// baseline (speedup 1.0000x reference)
#include <cuda_runtime.h>
#include <cuda_bf16.h>
#include <cstdint>

// Problem constants
#define B_TOTAL     16384
#define NUM_SPARSE  26
#define EMB         64
#define NCHUNK      28          // user + item + 26 sparse
#define HIDDEN      128
#define SPARSE_VOCAB 100000

#define TILE_B      64
#define THREADS     256
#define NUM_CTAS    (B_TOTAL / TILE_B)   // 256

// Shared memory strides (floats), padded for conflict-free fragment loads
#define A_STRIDE    68          // 64 + 4  -> (stride%32)=4, lanes map g*4+tig : conflict-free
#define W_STRIDE    136         // 128 + 8 -> (stride%32)=8, lanes map tig*8+g : conflict-free

// Shared layout (floats):
//   A_s   [2][TILE_B][A_STRIDE]   = 8704
//   W_s   [2][64][W_STRIDE]       = 17408
//   ids_s [NCHUNK][TILE_B] (int)  = 1792
//   b1_s  [HIDDEN]                = 128
//   w2_s  [HIDDEN]                = 128
//   rowsum[TILE_B]                = 64
#define A_ELEMS   (2 * TILE_B * A_STRIDE)
#define W_ELEMS   (2 * 64 * W_STRIDE)
#define IDS_ELEMS (NCHUNK * TILE_B)
#define SMEM_FLOATS (A_ELEMS + W_ELEMS + IDS_ELEMS + HIDDEN + HIDDEN + TILE_B)
#define SMEM_BYTES  (SMEM_FLOATS * 4)

__device__ __forceinline__ void cp16(float* dst, const float* src) {
    uint32_t d = (uint32_t)__cvta_generic_to_shared(dst);
    asm volatile("cp.async.cg.shared.global [%0], [%1], 16;" :: "r"(d), "l"(src) : "memory");
}

__device__ __forceinline__ void mma_tf32(float* c, const uint32_t* a, const uint32_t* b) {
    asm volatile(
        "mma.sync.aligned.m16n8k8.row.col.f32.tf32.tf32.f32 "
        "{%0,%1,%2,%3}, {%4,%5,%6,%7}, {%8,%9}, {%0,%1,%2,%3};\n"
        : "+f"(c[0]), "+f"(c[1]), "+f"(c[2]), "+f"(c[3])
        : "r"(a[0]), "r"(a[1]), "r"(a[2]), "r"(a[3]),
          "r"(b[0]), "r"(b[1]));
}

__global__ void __launch_bounds__(THREADS)
dlrm_fused_kernel(const int* __restrict__ user_ids,
                  const int* __restrict__ item_ids,
                  const int* __restrict__ sparse_features,
                  const float* __restrict__ user_emb,
                  const float* __restrict__ item_emb,
                  const float* __restrict__ sparse_tables,
                  const float* __restrict__ W1,
                  const float* __restrict__ b1,
                  const float* __restrict__ W2,
                  const float* __restrict__ b2,
                  float* __restrict__ out)
{
    extern __shared__ float smem[];
    float* A_s    = smem;                         // [2][TILE_B][A_STRIDE]
    float* W_s    = A_s + A_ELEMS;                // [2][64][W_STRIDE]
    int*   ids_s  = (int*)(W_s + W_ELEMS);        // [NCHUNK][TILE_B]
    float* b1_s   = (float*)(ids_s + IDS_ELEMS);
    float* w2_s   = b1_s + HIDDEN;
    float* rowsum = w2_s + HIDDEN;

    const int tid  = threadIdx.x;
    const int row0 = blockIdx.x * TILE_B;

    // ---------- init: ids, bias, W2, rowsum ----------
    if (tid < TILE_B) {
        ids_s[0 * TILE_B + tid] = user_ids[row0 + tid];
        ids_s[1 * TILE_B + tid] = item_ids[row0 + tid];
    }
    for (int i = tid; i < TILE_B * NUM_SPARSE; i += THREADS) {
        int r = i / NUM_SPARSE;
        int j = i % NUM_SPARSE;
        ids_s[(2 + j) * TILE_B + r] = sparse_features[(size_t)(row0 + r) * NUM_SPARSE + j];
    }
    if (tid < HIDDEN) {
        b1_s[tid] = b1[tid];
        w2_s[tid] = W2[tid];
    }
    if (tid < TILE_B) rowsum[tid] = 0.0f;
    __syncthreads();

    // ---------- staging lambda: gather A chunk + W1 chunk via cp.async ----------
    auto stage = [&](int f, int buf) {
        // A: 64 rows x 64 floats (256B per row). 4 threads per row, 4 x 16B each.
        const int r   = tid >> 2;
        const int seg = tid & 3;
        const int idx = ids_s[f * TILE_B + r];
        const float* src;
        if (f == 0)      src = user_emb + (size_t)idx * EMB;
        else if (f == 1) src = item_emb + (size_t)idx * EMB;
        else             src = sparse_tables + ((size_t)(f - 2) * SPARSE_VOCAB + (size_t)idx) * EMB;
        float* adst = A_s + buf * (TILE_B * A_STRIDE) + r * A_STRIDE;
        #pragma unroll
        for (int i = 0; i < 4; i++)
            cp16(adst + (seg + 4 * i) * 4, src + (seg + 4 * i) * 4);

        // W1 chunk: rows f*64 .. f*64+63, all 128 cols. 2048 float4 / 256 thr = 8 each.
        const float* wsrc = W1 + (size_t)f * 64 * HIDDEN;
        float* wdst = W_s + buf * (64 * W_STRIDE);
        #pragma unroll
        for (int i = 0; i < 8; i++) {
            int f4 = tid + THREADS * i;
            int k  = f4 >> 5;        // 32 float4 per row
            int c4 = f4 & 31;
            cp16(wdst + k * W_STRIDE + c4 * 4, wsrc + k * HIDDEN + c4 * 4);
        }
        asm volatile("cp.async.commit_group;" ::: "memory");
    };

    // ---------- warp tiling: 2 (M) x 4 (N), warp tile 32x32 ----------
    const int lane = tid & 31;
    const int warp = tid >> 5;
    const int wm   = (warp & 1) * 32;     // M offset within 64
    const int wn   = (warp >> 1) * 32;    // N offset within 128
    const int g    = lane >> 2;           // groupID
    const int tig  = lane & 3;            // threadID_in_group

    float acc[2][4][4];                   // [mtile][ntile][c0..c3]
    #pragma unroll
    for (int mt = 0; mt < 2; mt++)
        #pragma unroll
        for (int nt = 0; nt < 4; nt++)
            #pragma unroll
            for (int i = 0; i < 4; i++) acc[mt][nt][i] = 0.0f;

    stage(0, 0);

    // ---------- main loop over 28 K-chunks of 64 ----------
    for (int f = 0; f < NCHUNK; f++) {
        const int buf = f & 1;
        if (f + 1 < NCHUNK) {
            stage(f + 1, buf ^ 1);
            asm volatile("cp.async.wait_group 1;" ::: "memory");
        } else {
            asm volatile("cp.async.wait_group 0;" ::: "memory");
        }
        __syncthreads();

        const uint32_t* Ab = (const uint32_t*)(A_s + buf * (TILE_B * A_STRIDE));
        const uint32_t* Wb = (const uint32_t*)(W_s + buf * (64 * W_STRIDE));

        #pragma unroll
        for (int ks = 0; ks < 8; ks++) {
            const int k = ks * 8;
            uint32_t afrag[2][4];
            uint32_t bfrag[4][2];
            #pragma unroll
            for (int mt = 0; mt < 2; mt++) {
                const int mrow = wm + mt * 16;
                afrag[mt][0] = Ab[(mrow + g)     * A_STRIDE + k + tig];
                afrag[mt][1] = Ab[(mrow + g + 8) * A_STRIDE + k + tig];
                afrag[mt][2] = Ab[(mrow + g)     * A_STRIDE + k + tig + 4];
                afrag[mt][3] = Ab[(mrow + g + 8) * A_STRIDE + k + tig + 4];
            }
            #pragma unroll
            for (int nt = 0; nt < 4; nt++) {
                const int nc = wn + nt * 8 + g;
                bfrag[nt][0] = Wb[(k + tig)     * W_STRIDE + nc];
                bfrag[nt][1] = Wb[(k + tig + 4) * W_STRIDE + nc];
            }
            #pragma unroll
            for (int mt = 0; mt < 2; mt++)
                #pragma unroll
                for (int nt = 0; nt < 4; nt++)
                    mma_tf32(acc[mt][nt], afrag[mt], bfrag[nt]);
        }
        __syncthreads();  // release buffer before it is restaged
    }

    // ---------- epilogue: bias + relu + dot(W2) + reduce + sigmoid ----------
    #pragma unroll
    for (int mt = 0; mt < 2; mt++) {
        float p0 = 0.0f;   // row wm + mt*16 + g
        float p1 = 0.0f;   // row wm + mt*16 + g + 8
        #pragma unroll
        for (int nt = 0; nt < 4; nt++) {
            const int col = wn + nt * 8 + 2 * tig;
            const float b1a = b1_s[col],     b1b = b1_s[col + 1];
            const float w2a = w2_s[col],     w2b = w2_s[col + 1];
            p0 += fmaxf(acc[mt][nt][0] + b1a, 0.0f) * w2a
                + fmaxf(acc[mt][nt][1] + b1b, 0.0f) * w2b;
            p1 += fmaxf(acc[mt][nt][2] + b1a, 0.0f) * w2a
                + fmaxf(acc[mt][nt][3] + b1b, 0.0f) * w2b;
        }
        // reduce over tig (lane bits 0..1)
        p0 += __shfl_xor_sync(0xffffffffu, p0, 1);
        p0 += __shfl_xor_sync(0xffffffffu, p0, 2);
        p1 += __shfl_xor_sync(0xffffffffu, p1, 1);
        p1 += __shfl_xor_sync(0xffffffffu, p1, 2);
        if (tig == 0) {
            atomicAdd(&rowsum[wm + mt * 16 + g],     p0);
            atomicAdd(&rowsum[wm + mt * 16 + g + 8], p1);
        }
    }
    __syncthreads();

    if (tid < TILE_B) {
        const float raw = rowsum[tid] + b2[0];
        out[row0 + tid] = 1.0f / (1.0f + expf(-raw));
    }
}

extern "C" void kernel_launch(void* const* d_in, const int* in_sizes, int n_in,
                              void* d_out, int out_size)
{
    const int*   user_ids        = (const int*)d_in[0];
    const int*   item_ids        = (const int*)d_in[1];
    const int*   sparse_features = (const int*)d_in[2];
    const float* user_emb        = (const float*)d_in[3];
    const float* item_emb        = (const float*)d_in[4];
    const float* sparse_tables   = (const float*)d_in[5];
    const float* W1              = (const float*)d_in[6];
    const float* b1              = (const float*)d_in[7];
    const float* W2              = (const float*)d_in[8];
    const float* b2              = (const float*)d_in[9];
    float*       out             = (float*)d_out;

    cudaFuncSetAttribute(dlrm_fused_kernel,
                         cudaFuncAttributeMaxDynamicSharedMemorySize, SMEM_BYTES);

    dlrm_fused_kernel<<<NUM_CTAS, THREADS, SMEM_BYTES>>>(
        user_ids, item_ids, sparse_features,
        user_emb, item_emb, sparse_tables,
        W1, b1, W2, b2, out);
}